// round 5
// baseline (speedup 1.0000x reference)
#include <cuda_runtime.h>
#include <math.h>

#define NN 400000
#define NE 1600000
#define FIN 100
#define EMB 128
#define NG 11
#define SORTK 64
#define DCAT 385          // 3*EMB + 1
#define NEG_INF (-3.402823466e38f)

// ---------------- scratch (device globals; no allocation allowed) ----------
__device__ float g_deg[NN];
__device__ float g_selfnorm[NN];
__device__ float g_dis[NN];
__device__ float g_enorm[NE];
__device__ float g_h[(size_t)NN * EMB];   // pre-aggregation h = x@W
__device__ float g_x1[(size_t)NN * EMB];
__device__ float g_x2[(size_t)NN * EMB];
__device__ float g_x3[(size_t)NN * EMB];
__device__ float g_h4[NN];
__device__ float g_x4[NN];
__device__ float g_score[NN];
__device__ int   g_counts[NG];
__device__ int   g_starts[NG + 1];
__device__ int   g_sel[NG * SORTK];
__device__ float g_pooled[NG * SORTK * DCAT];
__device__ float g_h5[NG * 64 * 64];
__device__ float g_h5p[NG * 64 * 32];
__device__ float g_emb[NG * EMB * 28];
__device__ float g_fc1[128];

// ---------------- degree / norm prep ----------------
__global__ void k_init_deg() {
    int i = blockIdx.x * blockDim.x + threadIdx.x;
    if (i < NN) g_deg[i] = 1.0f;
}

__global__ void k_deg_acc(const int* __restrict__ ei) {
    int e = blockIdx.x * blockDim.x + threadIdx.x;
    if (e >= NE) return;
    int s = ei[e], d = ei[NE + e];
    if (s != d) atomicAdd(&g_deg[d], 1.0f);
}

__global__ void k_norms() {
    int i = blockIdx.x * blockDim.x + threadIdx.x;
    if (i >= NN) return;
    float dg = g_deg[i];
    g_selfnorm[i] = 1.0f / dg;
    g_dis[i] = rsqrtf(dg);
}

__global__ void k_enorm(const int* __restrict__ ei) {
    int e = blockIdx.x * blockDim.x + threadIdx.x;
    if (e >= NE) return;
    int s = ei[e], d = ei[NE + e];
    g_enorm[e] = (s != d) ? g_dis[s] * g_dis[d] : 0.0f;
}

__global__ void k_zero_counts() {
    int i = threadIdx.x;
    if (i < NG) g_counts[i] = 0;
}

__global__ void k_hist(const int* __restrict__ batch) {
    int i = blockIdx.x * blockDim.x + threadIdx.x;
    if (i < NN) atomicAdd(&g_counts[batch[i]], 1);
}

__global__ void k_scan() {
    g_starts[0] = 0;
    for (int g = 0; g < NG; g++) g_starts[g + 1] = g_starts[g] + g_counts[g];
}

// ---------------- SGEMM: C[M,128] = A[M,K] @ B[K,128] ----------------
// BM=64, BN=128, BK=16, 256 threads, each thread 8x4 outputs (strided).
__global__ __launch_bounds__(256) void k_sgemm(const float* __restrict__ A,
                                               const float* __restrict__ B,
                                               float* __restrict__ C,
                                               int K) {
    __shared__ float As[64][16];
    __shared__ float Bs[16][128];
    int tid  = threadIdx.x;
    int row0 = blockIdx.x * 64;
    int tcol = tid & 31;   // col lane: cols tcol + j*32
    int trow = tid >> 5;   // row group: rows trow + i*8

    float acc[8][4];
    #pragma unroll
    for (int i = 0; i < 8; i++)
        #pragma unroll
        for (int j = 0; j < 4; j++) acc[i][j] = 0.0f;

    for (int k0 = 0; k0 < K; k0 += 16) {
        #pragma unroll
        for (int i = 0; i < 4; i++) {
            int lin = tid + i * 256;
            int r = lin >> 4, c = lin & 15;
            int kk = k0 + c;
            As[r][c] = (kk < K) ? A[(size_t)(row0 + r) * K + kk] : 0.0f;
        }
        #pragma unroll
        for (int i = 0; i < 8; i++) {
            int lin = tid + i * 256;
            int r = lin >> 7, c = lin & 127;
            int kk = k0 + r;
            Bs[r][c] = (kk < K) ? B[kk * 128 + c] : 0.0f;
        }
        __syncthreads();
        #pragma unroll
        for (int kk = 0; kk < 16; kk++) {
            float bReg[4];
            #pragma unroll
            for (int j = 0; j < 4; j++) bReg[j] = Bs[kk][tcol + j * 32];
            #pragma unroll
            for (int i = 0; i < 8; i++) {
                float aV = As[trow + i * 8][kk];
                #pragma unroll
                for (int j = 0; j < 4; j++) acc[i][j] += aV * bReg[j];
            }
        }
        __syncthreads();
    }
    #pragma unroll
    for (int i = 0; i < 8; i++)
        #pragma unroll
        for (int j = 0; j < 4; j++)
            C[(size_t)(row0 + trow + i * 8) * 128 + tcol + j * 32] = acc[i][j];
}

// layer-4 row dot: h4[i] = dot(x3[i,:], W4)
__global__ void k_dotw4(const float* __restrict__ X, const float* __restrict__ W4) {
    int row  = blockIdx.x * 8 + (threadIdx.x >> 5);
    int lane = threadIdx.x & 31;
    if (row >= NN) return;
    const float4* xr = (const float4*)(X + (size_t)row * 128);
    const float4* w  = (const float4*)W4;
    float4 a = xr[lane];
    float4 b = w[lane];
    float s = a.x * b.x + a.y * b.y + a.z * b.z + a.w * b.w;
    #pragma unroll
    for (int o = 16; o > 0; o >>= 1) s += __shfl_xor_sync(0xffffffffu, s, o);
    if (lane == 0) g_h4[row] = s;
}

// out[i,j] = h[i,j]*selfnorm[i] + b[j]   (initializes the accumulator)
__global__ void k_initagg(const float* __restrict__ h, const float* __restrict__ b,
                          float* __restrict__ out) {
    int idx = blockIdx.x * blockDim.x + threadIdx.x;
    if (idx >= NN * EMB) return;
    out[idx] = h[idx] * g_selfnorm[idx >> 7] + b[idx & 127];
}

__global__ void k_initagg1(const float* __restrict__ b4) {
    int i = blockIdx.x * blockDim.x + threadIdx.x;
    if (i < NN) g_x4[i] = g_h4[i] * g_selfnorm[i] + b4[0];
}

// scatter: one warp per edge, 128 floats (float4 per lane), atomic add to dst
__global__ __launch_bounds__(256) void k_scatter128(const float* __restrict__ h,
                                                    float* __restrict__ out,
                                                    const int* __restrict__ ei) {
    int gtid = blockIdx.x * blockDim.x + threadIdx.x;
    int e    = gtid >> 5;
    int lane = gtid & 31;
    if (e >= NE) return;
    float w = g_enorm[e];
    if (w == 0.0f) return;
    int s = ei[e], d = ei[NE + e];
    float4 v = ((const float4*)(h + (size_t)s * 128))[lane];
    float* o = out + (size_t)d * 128 + lane * 4;
    atomicAdd(o + 0, v.x * w);
    atomicAdd(o + 1, v.y * w);
    atomicAdd(o + 2, v.z * w);
    atomicAdd(o + 3, v.w * w);
}

__global__ void k_scatter1(const int* __restrict__ ei) {
    int e = blockIdx.x * blockDim.x + threadIdx.x;
    if (e >= NE) return;
    float w = g_enorm[e];
    if (w == 0.0f) return;
    atomicAdd(&g_x4[ei[NE + e]], g_h4[ei[e]] * w);
}

__global__ void k_tanh(float* __restrict__ x, int n) {
    int i = blockIdx.x * blockDim.x + threadIdx.x;
    if (i < n) x[i] = tanhf(x[i]);
}

__global__ void k_tanh4() {
    int i = blockIdx.x * blockDim.x + threadIdx.x;
    if (i >= NN) return;
    float v = tanhf(g_x4[i]);
    g_x4[i] = v;
    g_score[i] = v;
}

// ---------------- per-graph top-64 (stable: larger score, tie -> lower idx) ----
__global__ __launch_bounds__(1024) void k_topk() {
    __shared__ float svals[1024];
    __shared__ int   sidx[1024];
    int g = blockIdx.x;
    int start = g_starts[g];
    int cnt   = g_counts[g];
    int tid   = threadIdx.x;
    for (int k = 0; k < SORTK; k++) {
        float best = NEG_INF;
        int   bidx = 0x7fffffff;
        for (int i = start + tid; i < start + cnt; i += 1024) {
            float v = g_score[i];
            if (v > best || (v == best && i < bidx)) { best = v; bidx = i; }
        }
        svals[tid] = best; sidx[tid] = bidx;
        __syncthreads();
        for (int s = 512; s > 0; s >>= 1) {
            if (tid < s) {
                float v2 = svals[tid + s]; int i2 = sidx[tid + s];
                if (v2 > svals[tid] || (v2 == svals[tid] && i2 < sidx[tid])) {
                    svals[tid] = v2; sidx[tid] = i2;
                }
            }
            __syncthreads();
        }
        if (tid == 0) {
            int bi = (k < cnt && svals[0] > NEG_INF) ? sidx[0] : -1;
            g_sel[g * SORTK + k] = bi;
            if (bi >= 0) g_score[bi] = NEG_INF;
        }
        __syncthreads();
    }
}

// pooled[g, r, c] = xc[sel[g*64+r], c]  (zeros if sel < 0)
__global__ void k_pooled() {
    int idx = blockIdx.x * blockDim.x + threadIdx.x;
    if (idx >= NG * SORTK * DCAT) return;
    int r = idx / DCAT;
    int c = idx - r * DCAT;
    int sel = g_sel[r];
    float v = 0.0f;
    if (sel >= 0) {
        if      (c < 128) v = g_x1[(size_t)sel * 128 + c];
        else if (c < 256) v = g_x2[(size_t)sel * 128 + (c - 128)];
        else if (c < 384) v = g_x3[(size_t)sel * 128 + (c - 256)];
        else              v = g_x4[sel];
    }
    g_pooled[idx] = v;
}

// conv5 (stride==kernel==385): h5[g,c,t] = relu(dot(pooled[g,t,:], cw5[c,:]) + cb5[c])
__global__ void k_conv5(const float* __restrict__ cw5, const float* __restrict__ cb5) {
    __shared__ float row[DCAT];
    int gt = blockIdx.x;           // g*64 + t
    int g  = gt >> 6, t = gt & 63;
    const float* pr = g_pooled + (size_t)gt * DCAT;
    for (int k = threadIdx.x; k < DCAT; k += blockDim.x) row[k] = pr[k];
    __syncthreads();
    int c = threadIdx.x;
    if (c < 64) {
        float acc = cb5[c];
        const float* w = cw5 + c * DCAT;
        for (int k = 0; k < DCAT; k++) acc += row[k] * w[k];
        g_h5[(g * 64 + c) * 64 + t] = fmaxf(acc, 0.0f);
    }
}

__global__ void k_maxpool() {
    int idx = blockIdx.x * blockDim.x + threadIdx.x;
    if (idx >= NG * 64 * 32) return;
    int g = idx / 2048;
    int rem = idx - g * 2048;
    int c = rem >> 5, j = rem & 31;
    float a = g_h5[(g * 64 + c) * 64 + 2 * j];
    float b = g_h5[(g * 64 + c) * 64 + 2 * j + 1];
    g_h5p[idx] = fmaxf(a, b);
}

// conv6: out[g,o,t] = relu(sum_{c,k} h5p[g,c,t+k]*cw6[o,c,k] + cb6[o]), t<28
__global__ __launch_bounds__(256) void k_conv6(const float* __restrict__ cw6,
                                               const float* __restrict__ cb6) {
    __shared__ float sm[64 * 32];
    int g = blockIdx.x;
    for (int i = threadIdx.x; i < 2048; i += 256) sm[i] = g_h5p[g * 2048 + i];
    __syncthreads();
    for (int lin = threadIdx.x; lin < 128 * 28; lin += 256) {
        int o = lin / 28, t = lin - o * 28;
        float acc = cb6[o];
        for (int c = 0; c < 64; c++) {
            const float* w = cw6 + (o * 64 + c) * 5;
            const float* hr = sm + c * 32 + t;
            #pragma unroll
            for (int k = 0; k < 5; k++) acc += hr[k] * w[k];
        }
        g_emb[g * 3584 + lin] = fmaxf(acc, 0.0f);
    }
}

// fc1: g_fc1[j] = relu(dot(emb, fw1[j,:]) + fb1[j]);  one block per j
__global__ __launch_bounds__(256) void k_fc1(const float* __restrict__ fw1,
                                             const float* __restrict__ fb1) {
    __shared__ float red[256];
    int j = blockIdx.x;
    const float* w = fw1 + (size_t)j * (NG * 3584);
    float s = 0.0f;
    for (int i = threadIdx.x; i < NG * 3584; i += 256) s += g_emb[i] * w[i];
    red[threadIdx.x] = s;
    __syncthreads();
    for (int st = 128; st > 0; st >>= 1) {
        if (threadIdx.x < st) red[threadIdx.x] += red[threadIdx.x + st];
        __syncthreads();
    }
    if (threadIdx.x == 0) g_fc1[j] = fmaxf(red[0] + fb1[j], 0.0f);
}

__global__ void k_fc2(const float* __restrict__ fw2, const float* __restrict__ fb2,
                      float* __restrict__ out) {
    int t = threadIdx.x;
    if (t < 10) {
        float acc = fb2[t];
        for (int j = 0; j < 128; j++) acc += g_fc1[j] * fw2[t * 128 + j];
        out[t] = acc;
    }
}

// ---------------- host ----------------
static float* sym(const void* s) {
    void* p = nullptr;
    cudaGetSymbolAddress(&p, s);
    return (float*)p;
}

extern "C" void kernel_launch(void* const* d_in, const int* in_sizes, int n_in,
                              void* d_out, int out_size) {
    const float* x    = (const float*)d_in[0];
    const int*   ei   = (const int*)  d_in[1];
    const int*   batch= (const int*)  d_in[2];
    const float* W1   = (const float*)d_in[3];
    const float* b1   = (const float*)d_in[4];
    const float* W2   = (const float*)d_in[5];
    const float* b2   = (const float*)d_in[6];
    const float* W3   = (const float*)d_in[7];
    const float* b3   = (const float*)d_in[8];
    const float* W4   = (const float*)d_in[9];
    const float* b4   = (const float*)d_in[10];
    const float* cw5  = (const float*)d_in[11];
    const float* cb5  = (const float*)d_in[12];
    const float* cw6  = (const float*)d_in[13];
    const float* cb6  = (const float*)d_in[14];
    const float* fw1  = (const float*)d_in[15];
    const float* fb1  = (const float*)d_in[16];
    const float* fw2  = (const float*)d_in[17];
    const float* fb2  = (const float*)d_in[18];
    float* out = (float*)d_out;

    float* p_h  = sym(g_h);
    float* p_x1 = sym(g_x1);
    float* p_x2 = sym(g_x2);
    float* p_x3 = sym(g_x3);

    const int NB_N   = (NN + 255) / 256;       // node-wise
    const int NB_E   = (NE + 255) / 256;       // edge-wise
    const int NB_NE  = (NN * EMB + 255) / 256; // node*feature-wise
    const int NB_SC  = (NE * 32 + 255) / 256;  // warp-per-edge scatter

    // prep
    k_init_deg<<<NB_N, 256>>>();
    k_deg_acc<<<NB_E, 256>>>(ei);
    k_norms<<<NB_N, 256>>>();
    k_enorm<<<NB_E, 256>>>(ei);
    k_zero_counts<<<1, 32>>>();
    k_hist<<<NB_N, 256>>>(batch);
    k_scan<<<1, 1>>>();

    // GCN layer 1
    k_sgemm<<<NN / 64, 256>>>(x, W1, p_h, FIN);
    k_initagg<<<NB_NE, 256>>>(p_h, b1, p_x1);
    k_scatter128<<<NB_SC, 256>>>(p_h, p_x1, ei);
    k_tanh<<<NB_NE, 256>>>(p_x1, NN * EMB);

    // GCN layer 2
    k_sgemm<<<NN / 64, 256>>>(p_x1, W2, p_h, EMB);
    k_initagg<<<NB_NE, 256>>>(p_h, b2, p_x2);
    k_scatter128<<<NB_SC, 256>>>(p_h, p_x2, ei);
    k_tanh<<<NB_NE, 256>>>(p_x2, NN * EMB);

    // GCN layer 3
    k_sgemm<<<NN / 64, 256>>>(p_x2, W3, p_h, EMB);
    k_initagg<<<NB_NE, 256>>>(p_h, b3, p_x3);
    k_scatter128<<<NB_SC, 256>>>(p_h, p_x3, ei);
    k_tanh<<<NB_NE, 256>>>(p_x3, NN * EMB);

    // GCN layer 4 (output dim 1)
    k_dotw4<<<NN / 8, 256>>>(p_x3, W4);
    k_initagg1<<<NB_N, 256>>>(b4);
    k_scatter1<<<NB_E, 256>>>(ei);
    k_tanh4<<<NB_N, 256>>>();

    // SortPool: per-graph top-64
    k_topk<<<NG, 1024>>>();
    k_pooled<<<(NG * SORTK * DCAT + 255) / 256, 256>>>();

    // tail
    k_conv5<<<NG * 64, 128>>>(cw5, cb5);
    k_maxpool<<<(NG * 64 * 32 + 255) / 256, 256>>>();
    k_conv6<<<NG, 256>>>(cw6, cb6);
    k_fc1<<<128, 256>>>(fw1, fb1);
    k_fc2<<<1, 32>>>(fw2, fb2, out);
}

// round 6
// speedup vs baseline: 2.0435x; 2.0435x over previous
#include <cuda_runtime.h>
#include <math.h>

#define NN 400000
#define NE 1600000
#define FIN 100
#define EMB 128
#define NG 11
#define SORTK 64
#define DCAT 385          // 3*EMB + 1
#define NEG_INF (-3.402823466e38f)

// ---------------- scratch (device globals; no allocation allowed) ----------
__device__ float g_selfnorm[NN];
__device__ float g_dis[NN];
__device__ float g_h[(size_t)NN * EMB];   // pre-aggregation h = x@W
__device__ float g_x1[(size_t)NN * EMB];
__device__ float g_x2[(size_t)NN * EMB];
__device__ float g_x3[(size_t)NN * EMB];
__device__ float g_h4[NN];
__device__ float g_x4[NN];
__device__ float g_score[NN];
__device__ int   g_counts[NG];
__device__ int   g_starts[NG + 1];
__device__ int   g_sel[NG * SORTK];
__device__ float g_pooled[NG * SORTK * DCAT];
__device__ float g_h5[NG * 64 * 64];
__device__ float g_h5p[NG * 64 * 32];
__device__ float g_emb[NG * EMB * 28];
__device__ float g_fc1[128];

// CSR (incoming edges grouped by dst)
__device__ int   g_indeg[NN];     // # incoming edges with s != d
__device__ int   g_incl[NN];      // block-local inclusive scan
__device__ int   g_part[1024];    // per-block partial sums
__device__ int   g_poff[1024];    // exclusive offsets of partials
__device__ int   g_cstart[NN];    // CSR row start
__device__ int   g_ccur[NN];      // fill cursor
__device__ int   g_csrc[NE];      // src node per CSR slot
__device__ float g_cw[NE];        // edge weight dis[s]*dis[d]

#define SCAN_B 512
#define SCAN_NB ((NN + SCAN_B - 1) / SCAN_B)   // 782

// ---------------- prep: degree, norms, CSR ----------------
__global__ void k_zero_indeg() {
    int i = blockIdx.x * blockDim.x + threadIdx.x;
    if (i < NN) g_indeg[i] = 0;
}

__global__ void k_count(const int* __restrict__ ei) {
    int e = blockIdx.x * blockDim.x + threadIdx.x;
    if (e >= NE) return;
    int s = ei[e], d = ei[NE + e];
    if (s != d) atomicAdd(&g_indeg[d], 1);
}

__global__ void k_norms() {
    int i = blockIdx.x * blockDim.x + threadIdx.x;
    if (i >= NN) return;
    float dg = (float)(g_indeg[i] + 1);
    g_selfnorm[i] = 1.0f / dg;
    g_dis[i] = rsqrtf(dg);
}

__global__ __launch_bounds__(SCAN_B) void k_scan1() {
    __shared__ int sm[SCAN_B];
    int tid = threadIdx.x;
    int i = blockIdx.x * SCAN_B + tid;
    int v = (i < NN) ? g_indeg[i] : 0;
    sm[tid] = v;
    __syncthreads();
    #pragma unroll
    for (int off = 1; off < SCAN_B; off <<= 1) {
        int t = (tid >= off) ? sm[tid - off] : 0;
        __syncthreads();
        sm[tid] += t;
        __syncthreads();
    }
    if (i < NN) g_incl[i] = sm[tid];
    if (tid == SCAN_B - 1) g_part[blockIdx.x] = sm[tid];
}

__global__ __launch_bounds__(1024) void k_scan2() {
    __shared__ int sm[1024];
    int tid = threadIdx.x;
    int v = (tid < SCAN_NB) ? g_part[tid] : 0;
    sm[tid] = v;
    __syncthreads();
    #pragma unroll
    for (int off = 1; off < 1024; off <<= 1) {
        int t = (tid >= off) ? sm[tid - off] : 0;
        __syncthreads();
        sm[tid] += t;
        __syncthreads();
    }
    g_poff[tid] = sm[tid] - v;   // exclusive
}

__global__ void k_scan3() {
    int i = blockIdx.x * blockDim.x + threadIdx.x;
    if (i >= NN) return;
    int st = g_poff[i / SCAN_B] + g_incl[i] - g_indeg[i];
    g_cstart[i] = st;
    g_ccur[i] = st;
}

__global__ void k_fill(const int* __restrict__ ei) {
    int e = blockIdx.x * blockDim.x + threadIdx.x;
    if (e >= NE) return;
    int s = ei[e], d = ei[NE + e];
    if (s == d) return;
    int pos = atomicAdd(&g_ccur[d], 1);
    g_csrc[pos] = s;
    g_cw[pos] = g_dis[s] * g_dis[d];
}

__global__ void k_zero_counts() {
    int i = threadIdx.x;
    if (i < NG) g_counts[i] = 0;
}

__global__ void k_hist(const int* __restrict__ batch) {
    int i = blockIdx.x * blockDim.x + threadIdx.x;
    if (i < NN) atomicAdd(&g_counts[batch[i]], 1);
}

__global__ void k_scan() {
    g_starts[0] = 0;
    for (int g = 0; g < NG; g++) g_starts[g + 1] = g_starts[g] + g_counts[g];
}

// ---------------- SGEMM: C[M,128] = A[M,K] @ B[K,128] ----------------
// BM=128, BN=128, BK=8, 256 threads, 8x8 micro-tile, reg-prefetch pipeline.
#define BM 128
#define BN 128
#define BK 8
__global__ __launch_bounds__(256) void k_sgemm(const float* __restrict__ A,
                                               const float* __restrict__ B,
                                               float* __restrict__ C,
                                               int K) {
    __shared__ float As[BK][BM + 4];   // +4 pad: conflict-free transpose store
    __shared__ float Bs[BK][BN];
    int tid  = threadIdx.x;
    int row0 = blockIdx.x * BM;
    int aRow = tid >> 1;            // 0..127
    int aCol = (tid & 1) * 4;       // 0 or 4
    int bRow = tid >> 5;            // 0..7
    int bCol = (tid & 31) * 4;      // 0..124
    int tx = tid & 15, ty = tid >> 4;

    const float* Aptr = A + (size_t)(row0 + aRow) * K;

    float a_reg[4], b_reg[4];
    // prologue: tile 0 -> regs
    {
        int k = aCol;
        if (k + 4 <= K) {
            float4 t = *(const float4*)(Aptr + k);
            a_reg[0] = t.x; a_reg[1] = t.y; a_reg[2] = t.z; a_reg[3] = t.w;
        } else {
            #pragma unroll
            for (int j = 0; j < 4; j++) a_reg[j] = (k + j < K) ? Aptr[k + j] : 0.0f;
        }
        int kb = bRow;
        if (kb < K) {
            float4 t = *(const float4*)(B + kb * 128 + bCol);
            b_reg[0] = t.x; b_reg[1] = t.y; b_reg[2] = t.z; b_reg[3] = t.w;
        } else {
            b_reg[0] = b_reg[1] = b_reg[2] = b_reg[3] = 0.0f;
        }
    }

    float acc[8][8];
    #pragma unroll
    for (int i = 0; i < 8; i++)
        #pragma unroll
        for (int j = 0; j < 8; j++) acc[i][j] = 0.0f;

    int ntiles = (K + BK - 1) / BK;
    for (int t = 0; t < ntiles; t++) {
        // regs -> smem
        #pragma unroll
        for (int j = 0; j < 4; j++) As[aCol + j][aRow] = a_reg[j];
        *(float4*)&Bs[bRow][bCol] = make_float4(b_reg[0], b_reg[1], b_reg[2], b_reg[3]);
        __syncthreads();

        // prefetch next tile into regs
        if (t + 1 < ntiles) {
            int k0n = (t + 1) * BK;
            int k = k0n + aCol;
            if (k + 4 <= K) {
                float4 tt = *(const float4*)(Aptr + k);
                a_reg[0] = tt.x; a_reg[1] = tt.y; a_reg[2] = tt.z; a_reg[3] = tt.w;
            } else {
                #pragma unroll
                for (int j = 0; j < 4; j++) a_reg[j] = (k + j < K) ? Aptr[k + j] : 0.0f;
            }
            int kb = k0n + bRow;
            if (kb < K) {
                float4 tt = *(const float4*)(B + kb * 128 + bCol);
                b_reg[0] = tt.x; b_reg[1] = tt.y; b_reg[2] = tt.z; b_reg[3] = tt.w;
            } else {
                b_reg[0] = b_reg[1] = b_reg[2] = b_reg[3] = 0.0f;
            }
        }

        #pragma unroll
        for (int kk = 0; kk < BK; kk++) {
            float4 a0 = *(const float4*)&As[kk][ty * 4];
            float4 a1 = *(const float4*)&As[kk][64 + ty * 4];
            float4 b0 = *(const float4*)&Bs[kk][tx * 4];
            float4 b1 = *(const float4*)&Bs[kk][64 + tx * 4];
            float av[8] = {a0.x, a0.y, a0.z, a0.w, a1.x, a1.y, a1.z, a1.w};
            float bv[8] = {b0.x, b0.y, b0.z, b0.w, b1.x, b1.y, b1.z, b1.w};
            #pragma unroll
            for (int i = 0; i < 8; i++)
                #pragma unroll
                for (int j = 0; j < 8; j++) acc[i][j] += av[i] * bv[j];
        }
        __syncthreads();
    }

    #pragma unroll
    for (int i = 0; i < 8; i++) {
        int r = row0 + ((i < 4) ? (ty * 4 + i) : (64 + ty * 4 + (i - 4)));
        float* cr = C + (size_t)r * 128;
        *(float4*)(cr + tx * 4)      = make_float4(acc[i][0], acc[i][1], acc[i][2], acc[i][3]);
        *(float4*)(cr + 64 + tx * 4) = make_float4(acc[i][4], acc[i][5], acc[i][6], acc[i][7]);
    }
}

// ---------------- fused CSR aggregation + self term + bias + tanh ----------
// one warp per node; lane holds float4 (128 feats / 32 lanes)
__global__ __launch_bounds__(256) void k_agg(const float* __restrict__ h,
                                             float* __restrict__ xout,
                                             const float* __restrict__ bias) {
    int node = blockIdx.x * 8 + (threadIdx.x >> 5);
    int lane = threadIdx.x & 31;
    if (node >= NN) return;
    float4 acc = ((const float4*)(h + (size_t)node * 128))[lane];
    float sn = g_selfnorm[node];
    float4 bb = ((const float4*)bias)[lane];
    acc.x = acc.x * sn + bb.x;
    acc.y = acc.y * sn + bb.y;
    acc.z = acc.z * sn + bb.z;
    acc.w = acc.w * sn + bb.w;
    int s0 = g_cstart[node];
    int e0 = s0 + g_indeg[node];
    for (int j = s0; j < e0; j++) {
        int s = g_csrc[j];
        float w = g_cw[j];
        float4 v = ((const float4*)(h + (size_t)s * 128))[lane];
        acc.x += w * v.x;
        acc.y += w * v.y;
        acc.z += w * v.z;
        acc.w += w * v.w;
    }
    acc.x = tanhf(acc.x); acc.y = tanhf(acc.y);
    acc.z = tanhf(acc.z); acc.w = tanhf(acc.w);
    ((float4*)(xout + (size_t)node * 128))[lane] = acc;
}

// layer-4 row dot: h4[i] = dot(x3[i,:], W4)
__global__ void k_dotw4(const float* __restrict__ X, const float* __restrict__ W4) {
    int row  = blockIdx.x * 8 + (threadIdx.x >> 5);
    int lane = threadIdx.x & 31;
    if (row >= NN) return;
    const float4* xr = (const float4*)(X + (size_t)row * 128);
    const float4* w  = (const float4*)W4;
    float4 a = xr[lane];
    float4 b = w[lane];
    float s = a.x * b.x + a.y * b.y + a.z * b.z + a.w * b.w;
    #pragma unroll
    for (int o = 16; o > 0; o >>= 1) s += __shfl_xor_sync(0xffffffffu, s, o);
    if (lane == 0) g_h4[row] = s;
}

// layer-4 CSR aggregation: one thread per node
__global__ void k_agg4(const float* __restrict__ b4) {
    int i = blockIdx.x * blockDim.x + threadIdx.x;
    if (i >= NN) return;
    float acc = b4[0] + g_h4[i] * g_selfnorm[i];
    int s0 = g_cstart[i];
    int e0 = s0 + g_indeg[i];
    for (int j = s0; j < e0; j++)
        acc += g_cw[j] * g_h4[g_csrc[j]];
    float v = tanhf(acc);
    g_x4[i] = v;
    g_score[i] = v;
}

// ---------------- per-graph top-64 (stable: larger score, tie -> lower idx) ----
__global__ __launch_bounds__(1024) void k_topk() {
    __shared__ float svals[1024];
    __shared__ int   sidx[1024];
    int g = blockIdx.x;
    int start = g_starts[g];
    int cnt   = g_counts[g];
    int tid   = threadIdx.x;
    for (int k = 0; k < SORTK; k++) {
        float best = NEG_INF;
        int   bidx = 0x7fffffff;
        for (int i = start + tid; i < start + cnt; i += 1024) {
            float v = g_score[i];
            if (v > best || (v == best && i < bidx)) { best = v; bidx = i; }
        }
        svals[tid] = best; sidx[tid] = bidx;
        __syncthreads();
        for (int s = 512; s > 0; s >>= 1) {
            if (tid < s) {
                float v2 = svals[tid + s]; int i2 = sidx[tid + s];
                if (v2 > svals[tid] || (v2 == svals[tid] && i2 < sidx[tid])) {
                    svals[tid] = v2; sidx[tid] = i2;
                }
            }
            __syncthreads();
        }
        if (tid == 0) {
            int bi = (k < cnt && svals[0] > NEG_INF) ? sidx[0] : -1;
            g_sel[g * SORTK + k] = bi;
            if (bi >= 0) g_score[bi] = NEG_INF;
        }
        __syncthreads();
    }
}

// pooled[g, r, c] = xc[sel[g*64+r], c]  (zeros if sel < 0)
__global__ void k_pooled() {
    int idx = blockIdx.x * blockDim.x + threadIdx.x;
    if (idx >= NG * SORTK * DCAT) return;
    int r = idx / DCAT;
    int c = idx - r * DCAT;
    int sel = g_sel[r];
    float v = 0.0f;
    if (sel >= 0) {
        if      (c < 128) v = g_x1[(size_t)sel * 128 + c];
        else if (c < 256) v = g_x2[(size_t)sel * 128 + (c - 128)];
        else if (c < 384) v = g_x3[(size_t)sel * 128 + (c - 256)];
        else              v = g_x4[sel];
    }
    g_pooled[idx] = v;
}

// conv5 (stride==kernel==385): h5[g,c,t] = relu(dot(pooled[g,t,:], cw5[c,:]) + cb5[c])
__global__ void k_conv5(const float* __restrict__ cw5, const float* __restrict__ cb5) {
    __shared__ float row[DCAT];
    int gt = blockIdx.x;           // g*64 + t
    int g  = gt >> 6, t = gt & 63;
    const float* pr = g_pooled + (size_t)gt * DCAT;
    for (int k = threadIdx.x; k < DCAT; k += blockDim.x) row[k] = pr[k];
    __syncthreads();
    int c = threadIdx.x;
    if (c < 64) {
        float acc = cb5[c];
        const float* w = cw5 + c * DCAT;
        for (int k = 0; k < DCAT; k++) acc += row[k] * w[k];
        g_h5[(g * 64 + c) * 64 + t] = fmaxf(acc, 0.0f);
    }
}

__global__ void k_maxpool() {
    int idx = blockIdx.x * blockDim.x + threadIdx.x;
    if (idx >= NG * 64 * 32) return;
    int g = idx / 2048;
    int rem = idx - g * 2048;
    int c = rem >> 5, j = rem & 31;
    float a = g_h5[(g * 64 + c) * 64 + 2 * j];
    float b = g_h5[(g * 64 + c) * 64 + 2 * j + 1];
    g_h5p[idx] = fmaxf(a, b);
}

// conv6: out[g,o,t] = relu(sum_{c,k} h5p[g,c,t+k]*cw6[o,c,k] + cb6[o]), t<28
__global__ __launch_bounds__(256) void k_conv6(const float* __restrict__ cw6,
                                               const float* __restrict__ cb6) {
    __shared__ float sm[64 * 32];
    int g = blockIdx.x;
    for (int i = threadIdx.x; i < 2048; i += 256) sm[i] = g_h5p[g * 2048 + i];
    __syncthreads();
    for (int lin = threadIdx.x; lin < 128 * 28; lin += 256) {
        int o = lin / 28, t = lin - o * 28;
        float acc = cb6[o];
        for (int c = 0; c < 64; c++) {
            const float* w = cw6 + (o * 64 + c) * 5;
            const float* hr = sm + c * 32 + t;
            #pragma unroll
            for (int k = 0; k < 5; k++) acc += hr[k] * w[k];
        }
        g_emb[g * 3584 + lin] = fmaxf(acc, 0.0f);
    }
}

// fc1: g_fc1[j] = relu(dot(emb, fw1[j,:]) + fb1[j]);  one block per j
__global__ __launch_bounds__(256) void k_fc1(const float* __restrict__ fw1,
                                             const float* __restrict__ fb1) {
    __shared__ float red[256];
    int j = blockIdx.x;
    const float* w = fw1 + (size_t)j * (NG * 3584);
    float s = 0.0f;
    for (int i = threadIdx.x; i < NG * 3584; i += 256) s += g_emb[i] * w[i];
    red[threadIdx.x] = s;
    __syncthreads();
    for (int st = 128; st > 0; st >>= 1) {
        if (threadIdx.x < st) red[threadIdx.x] += red[threadIdx.x + st];
        __syncthreads();
    }
    if (threadIdx.x == 0) g_fc1[j] = fmaxf(red[0] + fb1[j], 0.0f);
}

__global__ void k_fc2(const float* __restrict__ fw2, const float* __restrict__ fb2,
                      float* __restrict__ out) {
    int t = threadIdx.x;
    if (t < 10) {
        float acc = fb2[t];
        for (int j = 0; j < 128; j++) acc += g_fc1[j] * fw2[t * 128 + j];
        out[t] = acc;
    }
}

// ---------------- host ----------------
static float* sym(const void* s) {
    void* p = nullptr;
    cudaGetSymbolAddress(&p, s);
    return (float*)p;
}

extern "C" void kernel_launch(void* const* d_in, const int* in_sizes, int n_in,
                              void* d_out, int out_size) {
    const float* x    = (const float*)d_in[0];
    const int*   ei   = (const int*)  d_in[1];
    const int*   batch= (const int*)  d_in[2];
    const float* W1   = (const float*)d_in[3];
    const float* b1   = (const float*)d_in[4];
    const float* W2   = (const float*)d_in[5];
    const float* b2   = (const float*)d_in[6];
    const float* W3   = (const float*)d_in[7];
    const float* b3   = (const float*)d_in[8];
    const float* W4   = (const float*)d_in[9];
    const float* b4   = (const float*)d_in[10];
    const float* cw5  = (const float*)d_in[11];
    const float* cb5  = (const float*)d_in[12];
    const float* cw6  = (const float*)d_in[13];
    const float* cb6  = (const float*)d_in[14];
    const float* fw1  = (const float*)d_in[15];
    const float* fb1  = (const float*)d_in[16];
    const float* fw2  = (const float*)d_in[17];
    const float* fb2  = (const float*)d_in[18];
    float* out = (float*)d_out;

    float* p_h  = sym(g_h);
    float* p_x1 = sym(g_x1);
    float* p_x2 = sym(g_x2);
    float* p_x3 = sym(g_x3);

    const int NB_N  = (NN + 255) / 256;   // node-wise
    const int NB_E  = (NE + 255) / 256;   // edge-wise
    const int NB_W  = (NN + 7) / 8;       // warp-per-node

    // prep: degree + norms + CSR + batch offsets
    k_zero_indeg<<<NB_N, 256>>>();
    k_count<<<NB_E, 256>>>(ei);
    k_norms<<<NB_N, 256>>>();
    k_scan1<<<SCAN_NB, SCAN_B>>>();
    k_scan2<<<1, 1024>>>();
    k_scan3<<<NB_N, 256>>>();
    k_fill<<<NB_E, 256>>>(ei);
    k_zero_counts<<<1, 32>>>();
    k_hist<<<NB_N, 256>>>(batch);
    k_scan<<<1, 1>>>();

    // GCN layers 1-3: SGEMM + fused CSR aggregation (self + bias + tanh)
    k_sgemm<<<NN / BM, 256>>>(x, W1, p_h, FIN);
    k_agg<<<NB_W, 256>>>(p_h, p_x1, b1);

    k_sgemm<<<NN / BM, 256>>>(p_x1, W2, p_h, EMB);
    k_agg<<<NB_W, 256>>>(p_h, p_x2, b2);

    k_sgemm<<<NN / BM, 256>>>(p_x2, W3, p_h, EMB);
    k_agg<<<NB_W, 256>>>(p_h, p_x3, b3);

    // GCN layer 4 (output dim 1)
    k_dotw4<<<NN / 8, 256>>>(p_x3, W4);
    k_agg4<<<NB_N, 256>>>(b4);

    // SortPool: per-graph top-64
    k_topk<<<NG, 1024>>>();
    k_pooled<<<(NG * SORTK * DCAT + 255) / 256, 256>>>();

    // tail
    k_conv5<<<NG * 64, 128>>>(cw5, cb5);
    k_maxpool<<<(NG * 64 * 32 + 255) / 256, 256>>>();
    k_conv6<<<NG, 256>>>(cw6, cb6);
    k_fc1<<<128, 256>>>(fw1, fb1);
    k_fc2<<<1, 32>>>(fw2, fb2, out);
}